// round 6
// baseline (speedup 1.0000x reference)
#include <cuda_runtime.h>
#include <cstddef>

#define Bn     4
#define Cn     64
#define Hn     512
#define Wn     512
#define NSPIX  256
#define HW     (Hn*Wn)
#define HWH    (HW/2)

typedef unsigned long long ull;

// scratch
__device__ float g_spix [Bn*NSPIX*Cn];
__device__ float g_numer[Bn*NSPIX*Cn];
__device__ float g_denom2[2][Bn*NSPIX];

// ---- packed fp32x2 helpers ----
__device__ __forceinline__ ull f2_pack(float a, float b) {
    ull r; asm("mov.b64 %0, {%1,%2};" : "=l"(r) : "f"(a), "f"(b)); return r;
}
__device__ __forceinline__ void f2_unpack(ull v, float& a, float& b) {
    asm("mov.b64 {%0,%1}, %2;" : "=f"(a), "=f"(b) : "l"(v));
}
__device__ __forceinline__ void ffma2(ull& d, ull a, ull b) {
    asm("fma.rn.f32x2 %0, %1, %2, %0;" : "+l"(d) : "l"(a), "l"(b));
}

// shared layout (float offsets)
#define OFF_G    0                       // [9][64]
#define OFF_GSQ  576                     // [16]
#define OFF_DRED 592                     // [9][4] + pad -> 640
#define OFF_W    640                     // ull [9][130] pixel-pair weights
#define OFF_RED  2980                    // ull [128][21] phase-1 half-dot partials
#define OFF_F    8360                    // float2 [64][131] pixel-pair features
#define SMEM_FLOATS (8360 + 64*131*2)    // 25128 floats = 100512 B
#define SMEM_BYTES  (SMEM_FLOATS*4)
#define PSTRIDE 584                      // float partial stride per group (overlay on f)

// ---------------------------------------------------------------------------
__global__ void init_kernel(const float* __restrict__ f)
{
    __shared__ float sm[256];
    const int s = blockIdx.x, b = blockIdx.y;
    const int tid = threadIdx.x;
    const int c = tid & 63, part = tid >> 6;
    const int R = s >> 4, Cc = s & 15;
    const int y0 = R*32 + part*8, x0 = Cc*32;
    const float* fp = f + ((size_t)(b*Cn + c))*HW + (size_t)y0*Wn + x0;

    float sum = 0.f;
    for (int yy = 0; yy < 8; yy++) {
        const float4* r = (const float4*)(fp + (size_t)yy*Wn);
        #pragma unroll
        for (int x4 = 0; x4 < 8; x4++) {
            float4 v = r[x4];
            sum += (v.x + v.y) + (v.z + v.w);
        }
    }
    sm[tid] = sum;

    int gid = ((blockIdx.y*gridDim.x) + blockIdx.x)*256 + tid;
    if (gid < Bn*NSPIX*Cn) g_numer[gid] = 0.f;
    if (gid < 2*Bn*NSPIX)  ((float*)g_denom2)[gid] = 0.f;

    __syncthreads();
    if (tid < 64) {
        float t = sm[tid] + sm[64+tid] + sm[128+tid] + sm[192+tid];
        g_spix[(b*NSPIX + s)*Cn + tid] = t * (1.0f/1024.0f);
    }
}

// ---------------------------------------------------------------------------
// fused iteration kernel.  grid=(4,256,4)  block=256; tile 8x32 px
// phase 1: thread = (pair pi 0..127, channel-half h 0..1)
// ---------------------------------------------------------------------------
__global__ __launch_bounds__(256, 2)
void ssn_iter_kernel(const float* __restrict__ f,
                     float* __restrict__ out_labels,
                     int it, int last)
{
    extern __shared__ float sm[];
    float2* smf2 = (float2*)&sm[OFF_F];
    ull*    smw  = (ull*)&sm[OFF_W];
    ull*    red  = (ull*)&sm[OFF_RED];

    const int tid = threadIdx.x;
    const int bb = blockIdx.z, cell = blockIdx.y, q = blockIdx.x;
    const int R = cell >> 4, Cc = cell & 15;
    const int y0 = R*32 + q*8, x0 = Cc*32;
    const int par = it & 1;

    const int pi = tid & 127, h = tid >> 7;      // pair, channel-half
    const int prow = pi >> 4, pcol = (pi & 15)*2;

    int  nbr[9];
    bool valid[9];
    #pragma unroll
    for (int k = 0; k < 9; k++) {
        int rr = R + k/3 - 1, cc = Cc + (k%3) - 1;
        bool v = (rr >= 0) & (rr < 16) & (cc >= 0) & (cc < 16);
        valid[k] = v;
        nbr[k]   = v ? rr*16 + cc : 0;
    }

    // stage g (zero-filled invalid), zero dred
    for (int idx = tid; idx < 576; idx += 256) {
        int k = idx >> 6;
        sm[OFF_G + idx] = valid[k] ? g_spix[(bb*NSPIX + nbr[k])*Cn + (idx & 63)] : 0.f;
    }
    if (tid < 48) sm[OFF_DRED + tid] = 0.f;
    __syncthreads();

    if (tid < 9) {                       // ||g||^2
        float s = 0.f;
        #pragma unroll 8
        for (int c = 0; c < 64; c++) { float gv = sm[OFF_G + tid*64 + c]; s += gv*gv; }
        sm[OFF_GSQ + tid] = s;
    }

    // ---- phase 1: stream 32 channels of one pixel pair; stage float2; dots
    ull acc0[9], acc1[9], sva = 0ull, svb = 0ull;
    #pragma unroll
    for (int k = 0; k < 9; k++) { acc0[k] = 0ull; acc1[k] = 0ull; }
    {
        const float2* fp2 = (const float2*)(f
            + ((size_t)(bb*Cn + h*32))*HW + (size_t)(y0 + prow)*Wn + (x0 + pcol));
        const int cb = h*32;
        #pragma unroll 2
        for (int cs = 0; cs < 8; cs++) {
            const int c = cs*4;                     // local channel
            float2 u0 = fp2[(size_t)(c+0)*HWH];
            float2 u1 = fp2[(size_t)(c+1)*HWH];
            float2 u2 = fp2[(size_t)(c+2)*HWH];
            float2 u3 = fp2[(size_t)(c+3)*HWH];
            smf2[(cb+c+0)*131 + pi] = u0;
            smf2[(cb+c+1)*131 + pi] = u1;
            smf2[(cb+c+2)*131 + pi] = u2;
            smf2[(cb+c+3)*131 + pi] = u3;
            ull x01 = f2_pack(u0.x, u1.x), x23 = f2_pack(u2.x, u3.x);
            ull y01 = f2_pack(u0.y, u1.y), y23 = f2_pack(u2.y, u3.y);
            ffma2(sva, x01, x01); ffma2(sva, x23, x23);
            ffma2(svb, y01, y01); ffma2(svb, y23, y23);
            #pragma unroll
            for (int k = 0; k < 9; k++) {
                ulonglong2 g2 = *(const ulonglong2*)&sm[OFF_G + k*64 + cb + c];
                ffma2(acc0[k], x01, g2.x); ffma2(acc0[k], x23, g2.y);
                ffma2(acc1[k], y01, g2.x); ffma2(acc1[k], y23, g2.y);
            }
        }
    }
    // h=1 publishes its half-dots
    if (h == 1) {
        ull* r = &red[pi*21];
        #pragma unroll
        for (int k = 0; k < 9; k++) { r[k] = acc0[k]; r[9+k] = acc1[k]; }
        float a, b;
        f2_unpack(sva, a, b); float s0 = a + b;
        f2_unpack(svb, a, b); float s1 = a + b;
        r[18] = f2_pack(s0, s1);
    }
    __syncthreads();    // f tile, gsq, red all ready

    // ---- h=0: combine halves, softmax both pixels, labels, weights, denom
    if (h == 0) {
        const ull* r = &red[pi*21];
        float a, b;
        f2_unpack(sva, a, b); float sv0 = a + b;
        f2_unpack(svb, a, b); float sv1 = a + b;
        f2_unpack(r[18], a, b); sv0 += a; sv1 += b;

        float w0[9], w1[9];
        float dmin0 = 3.0e38f, dmin1 = 3.0e38f;
        #pragma unroll
        for (int k = 0; k < 9; k++) {
            float p0, p1;
            f2_unpack(acc0[k], a, b); f2_unpack(r[k], p0, p1);
            float d0 = valid[k] ? (sv0 - 2.f*(a + b + p0 + p1) + sm[OFF_GSQ + k]) : 3.0e38f;
            f2_unpack(acc1[k], a, b); f2_unpack(r[9+k], p0, p1);
            float d1 = valid[k] ? (sv1 - 2.f*(a + b + p0 + p1) + sm[OFF_GSQ + k]) : 3.0e38f;
            w0[k] = d0; w1[k] = d1;
            dmin0 = fminf(dmin0, d0); dmin1 = fminf(dmin1, d1);
        }
        if (last) {
            int k0 = 0, k1 = 0; float b0 = w0[0], b1 = w1[0];
            #pragma unroll
            for (int k = 1; k < 9; k++) {
                if (w0[k] < b0) { b0 = w0[k]; k0 = k; }
                if (w1[k] < b1) { b1 = w1[k]; k1 = k; }
            }
            size_t o = (size_t)bb*HW + (size_t)(y0 + prow)*Wn + (x0 + pcol);
            *(float2*)&out_labels[o] = make_float2((float)nbr[k0], (float)nbr[k1]);
        }
        float s0 = 0.f, s1 = 0.f;
        #pragma unroll
        for (int k = 0; k < 9; k++) {
            float e0 = __expf(dmin0 - w0[k]);
            float e1 = __expf(dmin1 - w1[k]);
            w0[k] = e0; w1[k] = e1; s0 += e0; s1 += e1;
        }
        float i0 = 1.f/s0, i1 = 1.f/s1;
        #pragma unroll
        for (int k = 0; k < 9; k++) {
            w0[k] *= i0; w1[k] *= i1;
            smw[k*130 + pi] = f2_pack(w0[k], w1[k]);
        }
        // denominators over the 4 h=0 warps
        #pragma unroll
        for (int k = 0; k < 9; k++) {
            float s = w0[k] + w1[k];
            s += __shfl_down_sync(0xffffffffu, s, 16);
            s += __shfl_down_sync(0xffffffffu, s, 8);
            s += __shfl_down_sync(0xffffffffu, s, 4);
            s += __shfl_down_sync(0xffffffffu, s, 2);
            s += __shfl_down_sync(0xffffffffu, s, 1);
            if ((tid & 31) == 0) sm[OFF_DRED + k*4 + (tid >> 5)] = s;
        }
    }
    __syncthreads();    // w + dred visible
    if (tid < 9 && valid[tid]) {
        const float* dr = &sm[OFF_DRED + tid*4];
        float s = (dr[0] + dr[1]) + (dr[2] + dr[3]);
        atomicAdd(&g_denom2[par][bb*NSPIX + nbr[tid]], s);
    }

    // ---- phase 2: pixel-pair packed accumulation
    // lane = channels (l, l+32); warp grp handles 16 pairs
    const int l   = tid & 31;
    const int grp = tid >> 5;
    ull m[18];
    #pragma unroll
    for (int k = 0; k < 18; k++) m[k] = 0ull;
    {
        const int prb = grp*16;
        #pragma unroll 2
        for (int jp = 0; jp < 8; jp++) {
            const int pr = prb + jp*2;
            ull A0 = *(const ull*)&smf2[ l      *131 + pr    ];
            ull A1 = *(const ull*)&smf2[ l      *131 + pr + 1];
            ull B0 = *(const ull*)&smf2[(l + 32)*131 + pr    ];
            ull B1 = *(const ull*)&smf2[(l + 32)*131 + pr + 1];
            #pragma unroll
            for (int k = 0; k < 9; k++) {
                ulonglong2 wv = *(const ulonglong2*)&smw[k*130 + pr];  // broadcast
                ffma2(m[k],     wv.x, A0);
                ffma2(m[k],     wv.y, A1);
                ffma2(m[k + 9], wv.x, B0);
                ffma2(m[k + 9], wv.y, B1);
            }
        }
    }
    __syncthreads();   // all f reads done -> overlay partials on f region

    {   // scalar partials: group-row, slot = k*64 + channel (conflict-free STS.32)
        float* part = &sm[OFF_F];
        #pragma unroll
        for (int k = 0; k < 9; k++) {
            float a, b;
            f2_unpack(m[k], a, b);
            part[(size_t)grp*PSTRIDE + k*64 + l]      = a + b;
            f2_unpack(m[k+9], a, b);
            part[(size_t)grp*PSTRIDE + k*64 + l + 32] = a + b;
        }
    }
    __syncthreads();

    {   // reduce 576 slots over 8 groups, then global RED.ADD
        const float* part = &sm[OFF_F];
        for (int s = tid; s < 576; s += 256) {
            float sum = part[s];
            #pragma unroll
            for (int g = 1; g < 8; g++) sum += part[(size_t)g*PSTRIDE + s];
            int k = s >> 6, c = s & 63;
            atomicAdd(&g_numer[(bb*NSPIX + nbr[k])*Cn + c], sum);  // invalid k adds 0.0
        }
    }
}

// ---------------------------------------------------------------------------
__global__ void update_kernel(float* __restrict__ out_spix, int it, int last)
{
    int idx = blockIdx.x*256 + threadIdx.x;     // 65536
    int par = it & 1;
    float val = g_numer[idx] / (g_denom2[par][idx >> 6] + 1e-16f);
    g_spix[idx] = val;
    if (last) out_spix[idx] = val;
    g_numer[idx] = 0.f;
    if (idx < Bn*NSPIX) g_denom2[1 - par][idx] = 0.f;
}

// ---------------------------------------------------------------------------
extern "C" void kernel_launch(void* const* d_in, const int* in_sizes, int n_in,
                              void* d_out, int out_size)
{
    const float* f = (const float*)d_in[0];
    float* out        = (float*)d_out;
    float* out_spix   = out;                       // (4,256,64)
    float* out_labels = out + Bn*NSPIX*Cn;         // (4,262144)

    cudaFuncSetAttribute(ssn_iter_kernel,
                         cudaFuncAttributeMaxDynamicSharedMemorySize, SMEM_BYTES);

    init_kernel<<<dim3(NSPIX, Bn), 256>>>(f);
    for (int it = 0; it < 5; it++) {
        ssn_iter_kernel<<<dim3(4, NSPIX, Bn), 256, SMEM_BYTES>>>(
            f, out_labels, it, it == 4);
        update_kernel<<<256, 256>>>(out_spix, it, it == 4);
    }
}

// round 7
// speedup vs baseline: 1.1041x; 1.1041x over previous
#include <cuda_runtime.h>
#include <cstddef>

#define Bn     4
#define Cn     64
#define Hn     512
#define Wn     512
#define NSPIX  256
#define HW     (Hn*Wn)

typedef unsigned long long ull;

// scratch
__device__ float g_spix [Bn*NSPIX*Cn];
__device__ float g_numer[Bn*NSPIX*Cn];
__device__ float g_denom2[2][Bn*NSPIX];

// ---- packed fp32x2 helpers ----
__device__ __forceinline__ ull f2_pack(float a, float b) {
    ull r; asm("mov.b64 %0, {%1,%2};" : "=l"(r) : "f"(a), "f"(b)); return r;
}
__device__ __forceinline__ void f2_unpack(ull v, float& a, float& b) {
    asm("mov.b64 {%0,%1}, %2;" : "=f"(a), "=f"(b) : "l"(v));
}
__device__ __forceinline__ void ffma2(ull& d, ull a, ull b) {
    asm("fma.rn.f32x2 %0, %1, %2, %0;" : "+l"(d) : "l"(a), "l"(b));
}

// shared layout (float offsets)
#define OFF_G    0                      // [9][64]
#define OFF_GSQ  576                    // [16]
#define OFF_DRED 592                    // [9][8], pad to 664 (16B align for W)
#define OFF_W    664                    // [9][260] floats; read as ull pairs
#define OFF_F    3004                   // [64][258] pixel-scalar floats (16B aligned)
#define FS       258                    // stride: FS/2=129 odd -> pair reads conflict-free
#define SMEM_FLOATS (3004 + 64*FS)      // 19516 floats = 78064 B
#define SMEM_BYTES  (SMEM_FLOATS*4)
#define PSTRIDE 584                     // float partial stride per warp-group (overlay on f)

// ---------------------------------------------------------------------------
__global__ void init_kernel(const float* __restrict__ f)
{
    __shared__ float sm[256];
    const int s = blockIdx.x, b = blockIdx.y;
    const int tid = threadIdx.x;
    const int c = tid & 63, part = tid >> 6;
    const int R = s >> 4, Cc = s & 15;
    const int y0 = R*32 + part*8, x0 = Cc*32;
    const float* fp = f + ((size_t)(b*Cn + c))*HW + (size_t)y0*Wn + x0;

    float sum = 0.f;
    for (int yy = 0; yy < 8; yy++) {
        const float4* r = (const float4*)(fp + (size_t)yy*Wn);
        #pragma unroll
        for (int x4 = 0; x4 < 8; x4++) {
            float4 v = r[x4];
            sum += (v.x + v.y) + (v.z + v.w);
        }
    }
    sm[tid] = sum;

    int gid = ((blockIdx.y*gridDim.x) + blockIdx.x)*256 + tid;
    if (gid < Bn*NSPIX*Cn) g_numer[gid] = 0.f;
    if (gid < 2*Bn*NSPIX)  ((float*)g_denom2)[gid] = 0.f;

    __syncthreads();
    if (tid < 64) {
        float t = sm[tid] + sm[64+tid] + sm[128+tid] + sm[192+tid];
        g_spix[(b*NSPIX + s)*Cn + tid] = t * (1.0f/1024.0f);
    }
}

// ---------------------------------------------------------------------------
// fused iteration kernel.  grid=(4,256,4)  block=256 (8x32 pixel tile)
// ---------------------------------------------------------------------------
__global__ __launch_bounds__(256, 2)
void ssn_iter_kernel(const float* __restrict__ f,
                     float* __restrict__ out_labels,
                     int it, int last)
{
    extern __shared__ float sm[];
    const int tid = threadIdx.x;
    const int bb = blockIdx.z, cell = blockIdx.y, q = blockIdx.x;
    const int R = cell >> 4, Cc = cell & 15;
    const int y0 = R*32 + q*8, x0 = Cc*32;
    const int par = it & 1;

    int  nbr[9];
    bool valid[9];
    #pragma unroll
    for (int k = 0; k < 9; k++) {
        int rr = R + k/3 - 1, cc = Cc + (k%3) - 1;
        bool v = (rr >= 0) & (rr < 16) & (cc >= 0) & (cc < 16);
        valid[k] = v;
        nbr[k]   = v ? rr*16 + cc : 0;
    }

    // stage g (zero-filled invalid), zero dred
    for (int idx = tid; idx < 576; idx += 256) {
        int k = idx >> 6;
        sm[OFF_G + idx] = valid[k] ? g_spix[(bb*NSPIX + nbr[k])*Cn + (idx & 63)] : 0.f;
    }
    if (tid < 72) sm[OFF_DRED + tid] = 0.f;
    __syncthreads();

    if (tid < 9) {                       // ||g||^2
        float s = 0.f;
        #pragma unroll 8
        for (int c = 0; c < 64; c++) { float gv = sm[OFF_G + tid*64 + c]; s += gv*gv; }
        sm[OFF_GSQ + tid] = s;
    }

    // ---- phase 1: per-pixel stream; scalar staging; channel-packed dots
    const int p = tid;
    ull acc[9], sv = 0ull;
    #pragma unroll
    for (int k = 0; k < 9; k++) acc[k] = 0ull;
    {
        const float* fp = f + ((size_t)bb*Cn)*HW
                            + (size_t)(y0 + (p >> 5))*Wn + (x0 + (p & 31));
        #pragma unroll 4
        for (int cs = 0; cs < 16; cs++) {
            const int c = cs*4;
            float v0 = fp[(size_t)(c+0)*HW];
            float v1 = fp[(size_t)(c+1)*HW];
            float v2 = fp[(size_t)(c+2)*HW];
            float v3 = fp[(size_t)(c+3)*HW];
            sm[OFF_F + (c+0)*FS + p] = v0;      // consecutive STS.32, conflict-free
            sm[OFF_F + (c+1)*FS + p] = v1;
            sm[OFF_F + (c+2)*FS + p] = v2;
            sm[OFF_F + (c+3)*FS + p] = v3;
            ull p01 = f2_pack(v0, v1);
            ull p23 = f2_pack(v2, v3);
            ffma2(sv, p01, p01);
            ffma2(sv, p23, p23);
            #pragma unroll
            for (int k = 0; k < 9; k++) {
                ulonglong2 g2 = *(const ulonglong2*)&sm[OFF_G + k*64 + c];  // broadcast
                ffma2(acc[k], p01, g2.x);
                ffma2(acc[k], p23, g2.y);
            }
        }
    }
    __syncthreads();   // gsq ready; f tile complete

    // ---- softmax per pixel (registers)
    float w[9];
    {
        float sa, sb; f2_unpack(sv, sa, sb);
        const float sv_s = sa + sb;
        float dmin = 3.0e38f;
        #pragma unroll
        for (int k = 0; k < 9; k++) {
            float a, b; f2_unpack(acc[k], a, b);
            float d = valid[k] ? (sv_s - 2.f*(a+b) + sm[OFF_GSQ + k]) : 3.0e38f;
            w[k] = d;
            dmin = fminf(dmin, d);
        }
        if (last) {
            int kb = 0; float bd = w[0];
            #pragma unroll
            for (int k = 1; k < 9; k++) if (w[k] < bd) { bd = w[k]; kb = k; }
            out_labels[(size_t)bb*HW + (size_t)(y0 + (p>>5))*Wn + (x0 + (p&31))]
                = (float)nbr[kb];
        }
        float s = 0.f;
        #pragma unroll
        for (int k = 0; k < 9; k++) { float e = __expf(dmin - w[k]); w[k] = e; s += e; }
        float inv = 1.f / s;
        #pragma unroll
        for (int k = 0; k < 9; k++) w[k] *= inv;
    }

    // scalar weight store into pair-addressable layout (conflict-free STS.32)
    #pragma unroll
    for (int k = 0; k < 9; k++) sm[OFF_W + k*260 + p] = w[k];

    // denominators: 9 block-wide sums
    #pragma unroll
    for (int k = 0; k < 9; k++) {
        float s = w[k];
        s += __shfl_down_sync(0xffffffffu, s, 16);
        s += __shfl_down_sync(0xffffffffu, s, 8);
        s += __shfl_down_sync(0xffffffffu, s, 4);
        s += __shfl_down_sync(0xffffffffu, s, 2);
        s += __shfl_down_sync(0xffffffffu, s, 1);
        if ((tid & 31) == 0) sm[OFF_DRED + k*8 + (tid >> 5)] = s;
    }
    __syncthreads();   // w + dred visible
    if (tid < 9 && valid[tid]) {
        const float* dr = &sm[OFF_DRED + tid*8];
        float s = ((dr[0]+dr[1]) + (dr[2]+dr[3])) + ((dr[4]+dr[5]) + (dr[6]+dr[7]));
        atomicAdd(&g_denom2[par][bb*NSPIX + nbr[tid]], s);
    }

    // ---- phase 2: pixel-pair packed, NO packs, NO shared atomics
    // lane = channels (l, l+32); warp grp owns 32 pixels (16 pairs)
    const int l   = tid & 31;
    const int grp = tid >> 5;
    ull m[18];
    #pragma unroll
    for (int k = 0; k < 18; k++) m[k] = 0ull;
    {
        const int pb = grp*32;               // first pixel of this warp's group
        #pragma unroll 2
        for (int jp = 0; jp < 8; jp++) {
            const int px = pb + jp*4;        // 4 pixels = 2 pairs per step
            ull A0 = *(const ull*)&sm[OFF_F +  l      *FS + px    ];
            ull A1 = *(const ull*)&sm[OFF_F +  l      *FS + px + 2];
            ull B0 = *(const ull*)&sm[OFF_F + (l + 32)*FS + px    ];
            ull B1 = *(const ull*)&sm[OFF_F + (l + 32)*FS + px + 2];
            #pragma unroll
            for (int k = 0; k < 9; k++) {
                ulonglong2 wv = *(const ulonglong2*)&sm[OFF_W + k*260 + px]; // broadcast
                ffma2(m[k],     wv.x, A0);
                ffma2(m[k],     wv.y, A1);
                ffma2(m[k + 9], wv.x, B0);
                ffma2(m[k + 9], wv.y, B1);
            }
        }
    }
    __syncthreads();   // all f reads done -> overlay partials on f region

    {   // scalar partials: group-row, slot = k*64 + channel (conflict-free STS.32)
        float* part = &sm[OFF_F];
        #pragma unroll
        for (int k = 0; k < 9; k++) {
            float a, b;
            f2_unpack(m[k], a, b);
            part[(size_t)grp*PSTRIDE + k*64 + l]      = a + b;
            f2_unpack(m[k+9], a, b);
            part[(size_t)grp*PSTRIDE + k*64 + l + 32] = a + b;
        }
    }
    __syncthreads();

    {   // reduce 576 slots over 8 groups, then global RED.ADD
        const float* part = &sm[OFF_F];
        for (int s = tid; s < 576; s += 256) {
            float sum = part[s];
            #pragma unroll
            for (int g = 1; g < 8; g++) sum += part[(size_t)g*PSTRIDE + s];
            int k = s >> 6, c = s & 63;
            atomicAdd(&g_numer[(bb*NSPIX + nbr[k])*Cn + c], sum);  // invalid k adds 0.0
        }
    }
}

// ---------------------------------------------------------------------------
__global__ void update_kernel(float* __restrict__ out_spix, int it, int last)
{
    int idx = blockIdx.x*256 + threadIdx.x;     // 65536
    int par = it & 1;
    float val = g_numer[idx] / (g_denom2[par][idx >> 6] + 1e-16f);
    g_spix[idx] = val;
    if (last) out_spix[idx] = val;
    g_numer[idx] = 0.f;
    if (idx < Bn*NSPIX) g_denom2[1 - par][idx] = 0.f;
}

// ---------------------------------------------------------------------------
extern "C" void kernel_launch(void* const* d_in, const int* in_sizes, int n_in,
                              void* d_out, int out_size)
{
    const float* f = (const float*)d_in[0];
    float* out        = (float*)d_out;
    float* out_spix   = out;                       // (4,256,64)
    float* out_labels = out + Bn*NSPIX*Cn;         // (4,262144)

    cudaFuncSetAttribute(ssn_iter_kernel,
                         cudaFuncAttributeMaxDynamicSharedMemorySize, SMEM_BYTES);

    init_kernel<<<dim3(NSPIX, Bn), 256>>>(f);
    for (int it = 0; it < 5; it++) {
        ssn_iter_kernel<<<dim3(4, NSPIX, Bn), 256, SMEM_BYTES>>>(
            f, out_labels, it, it == 4);
        update_kernel<<<256, 256>>>(out_spix, it, it == 4);
    }
}

// round 8
// speedup vs baseline: 1.2400x; 1.1230x over previous
#include <cuda_runtime.h>
#include <cstddef>

#define Bn     4
#define Cn     64
#define Hn     512
#define Wn     512
#define NSPIX  256
#define HW     (Hn*Wn)

typedef unsigned long long ull;

// scratch
__device__ float g_spix [Bn*NSPIX*Cn];
__device__ float g_numer[Bn*NSPIX*Cn];
__device__ float g_denom2[2][Bn*NSPIX];

// ---- packed fp32x2 helpers ----
__device__ __forceinline__ ull f2_pack(float a, float b) {
    ull r; asm("mov.b64 %0, {%1,%2};" : "=l"(r) : "f"(a), "f"(b)); return r;
}
__device__ __forceinline__ void f2_unpack(ull v, float& a, float& b) {
    asm("mov.b64 {%0,%1}, %2;" : "=f"(a), "=f"(b) : "l"(v));
}
__device__ __forceinline__ void ffma2(ull& d, ull a, ull b) {
    asm("fma.rn.f32x2 %0, %1, %2, %0;" : "+l"(d) : "l"(a), "l"(b));
}

// shared layout (float offsets), 128-px tile
#define OFF_G    0                      // [9][64]; DRED overlays [0..36) after dots
#define OFF_GSQ  576                    // [16]
#define OFF_W    592                    // [9][132] floats, rows 16B-aligned
#define OFF_F    1780                   // [64][130] pixel-scalar floats
#define FS       130                    // FS/2=65 odd -> pair reads conflict-free
#define SMEM_FLOATS (1780 + 64*FS)      // 10100 floats = 40400 B
#define SMEM_BYTES  (SMEM_FLOATS*4)
#define PSTRIDE 584                     // partial stride per warp-group (overlay on f)

__device__ __forceinline__ int nbr_of(int R, int Cc, int k) {
    return (R + k/3 - 1)*16 + (Cc + k%3 - 1);
}

// ---------------------------------------------------------------------------
__global__ void init_kernel(const float* __restrict__ f)
{
    __shared__ float sm[256];
    const int s = blockIdx.x, b = blockIdx.y;
    const int tid = threadIdx.x;
    const int c = tid & 63, part = tid >> 6;
    const int R = s >> 4, Cc = s & 15;
    const int y0 = R*32 + part*8, x0 = Cc*32;
    const float* fp = f + ((size_t)(b*Cn + c))*HW + (size_t)y0*Wn + x0;

    float sum = 0.f;
    for (int yy = 0; yy < 8; yy++) {
        const float4* r = (const float4*)(fp + (size_t)yy*Wn);
        #pragma unroll
        for (int x4 = 0; x4 < 8; x4++) {
            float4 v = r[x4];
            sum += (v.x + v.y) + (v.z + v.w);
        }
    }
    sm[tid] = sum;

    int gid = ((blockIdx.y*gridDim.x) + blockIdx.x)*256 + tid;
    if (gid < Bn*NSPIX*Cn) g_numer[gid] = 0.f;
    if (gid < 2*Bn*NSPIX)  ((float*)g_denom2)[gid] = 0.f;

    __syncthreads();
    if (tid < 64) {
        float t = sm[tid] + sm[64+tid] + sm[128+tid] + sm[192+tid];
        g_spix[(b*NSPIX + s)*Cn + tid] = t * (1.0f/1024.0f);
    }
}

// ---------------------------------------------------------------------------
// fused iteration kernel.  grid=(8,256,4)  block=128 (4x32 pixel tile)
// ---------------------------------------------------------------------------
__global__ __launch_bounds__(128, 5)
void ssn_iter_kernel(const float* __restrict__ f,
                     float* __restrict__ out_labels,
                     int it, int last)
{
    extern __shared__ float sm[];
    const int tid = threadIdx.x;
    const int bb = blockIdx.z, cell = blockIdx.y, q = blockIdx.x;
    const int R = cell >> 4, Cc = cell & 15;
    const int y0 = R*32 + q*4, x0 = Cc*32;
    const int par = it & 1;

    unsigned vmask = 0;
    #pragma unroll
    for (int k = 0; k < 9; k++) {
        int rr = R + k/3 - 1, cc = Cc + (k%3) - 1;
        if ((rr >= 0) & (rr < 16) & (cc >= 0) & (cc < 16)) vmask |= 1u << k;
    }

    // stage g (zero-filled invalid)
    for (int idx = tid; idx < 576; idx += 128) {
        int k = idx >> 6;
        int nb = nbr_of(R, Cc, k);
        sm[OFF_G + idx] = (vmask >> k & 1)
            ? g_spix[(bb*NSPIX + nb)*Cn + (idx & 63)] : 0.f;
    }
    __syncthreads();

    if (tid < 9) {                       // ||g||^2
        float s = 0.f;
        #pragma unroll 8
        for (int c = 0; c < 64; c++) { float gv = sm[OFF_G + tid*64 + c]; s += gv*gv; }
        sm[OFF_GSQ + tid] = s;
    }

    // ---- phase 1: per-pixel stream; scalar staging; channel-packed dots
    const int p = tid;
    ull acc[9], sv = 0ull;
    #pragma unroll
    for (int k = 0; k < 9; k++) acc[k] = 0ull;
    {
        const float* fp = f + ((size_t)bb*Cn)*HW
                            + (size_t)(y0 + (p >> 5))*Wn + (x0 + (p & 31));
        #pragma unroll 4
        for (int cs = 0; cs < 16; cs++) {
            const int c = cs*4;
            float v0 = fp[(size_t)(c+0)*HW];
            float v1 = fp[(size_t)(c+1)*HW];
            float v2 = fp[(size_t)(c+2)*HW];
            float v3 = fp[(size_t)(c+3)*HW];
            sm[OFF_F + (c+0)*FS + p] = v0;      // conflict-free STS.32
            sm[OFF_F + (c+1)*FS + p] = v1;
            sm[OFF_F + (c+2)*FS + p] = v2;
            sm[OFF_F + (c+3)*FS + p] = v3;
            ull p01 = f2_pack(v0, v1);
            ull p23 = f2_pack(v2, v3);
            ffma2(sv, p01, p01);
            ffma2(sv, p23, p23);
            #pragma unroll
            for (int k = 0; k < 9; k++) {
                ulonglong2 g2 = *(const ulonglong2*)&sm[OFF_G + k*64 + c];  // broadcast
                ffma2(acc[k], p01, g2.x);
                ffma2(acc[k], p23, g2.y);
            }
        }
    }
    __syncthreads();   // gsq ready; f tile complete; G dead after this point

    // ---- softmax per pixel (registers)
    float w[9];
    {
        float sa, sb; f2_unpack(sv, sa, sb);
        const float sv_s = sa + sb;
        float dmin = 3.0e38f;
        #pragma unroll
        for (int k = 0; k < 9; k++) {
            float a, b; f2_unpack(acc[k], a, b);
            float d = (vmask >> k & 1) ? (sv_s - 2.f*(a+b) + sm[OFF_GSQ + k]) : 3.0e38f;
            w[k] = d;
            dmin = fminf(dmin, d);
        }
        if (last) {
            int kb = 0; float bd = w[0];
            #pragma unroll
            for (int k = 1; k < 9; k++) if (w[k] < bd) { bd = w[k]; kb = k; }
            out_labels[(size_t)bb*HW + (size_t)(y0 + (p>>5))*Wn + (x0 + (p&31))]
                = (float)nbr_of(R, Cc, kb);
        }
        float s = 0.f;
        #pragma unroll
        for (int k = 0; k < 9; k++) { float e = __expf(dmin - w[k]); w[k] = e; s += e; }
        float inv = 1.f / s;
        #pragma unroll
        for (int k = 0; k < 9; k++) w[k] *= inv;
    }

    // scalar weight store into pair-addressable layout (conflict-free STS.32)
    #pragma unroll
    for (int k = 0; k < 9; k++) sm[OFF_W + k*132 + p] = w[k];

    // denominators: 9 block-wide sums -> dred overlays dead G region
    #pragma unroll
    for (int k = 0; k < 9; k++) {
        float s = w[k];
        s += __shfl_down_sync(0xffffffffu, s, 16);
        s += __shfl_down_sync(0xffffffffu, s, 8);
        s += __shfl_down_sync(0xffffffffu, s, 4);
        s += __shfl_down_sync(0xffffffffu, s, 2);
        s += __shfl_down_sync(0xffffffffu, s, 1);
        if ((tid & 31) == 0) sm[OFF_G + k*4 + (tid >> 5)] = s;
    }
    __syncthreads();   // w + dred visible
    if (tid < 9 && (vmask >> tid & 1)) {
        const float* dr = &sm[OFF_G + tid*4];
        float s = (dr[0] + dr[1]) + (dr[2] + dr[3]);
        atomicAdd(&g_denom2[par][bb*NSPIX + nbr_of(R, Cc, tid)], s);
    }

    // ---- phase 2: pixel-pair packed, no packs, no shared atomics
    // lane = channels (l, l+32); warp grp owns 32 pixels (16 pairs)
    const int l   = tid & 31;
    const int grp = tid >> 5;
    ull m[18];
    #pragma unroll
    for (int k = 0; k < 18; k++) m[k] = 0ull;
    {
        const int pb = grp*32;
        #pragma unroll 2
        for (int jp = 0; jp < 8; jp++) {
            const int px = pb + jp*4;        // 4 pixels = 2 pairs per step
            ull A0 = *(const ull*)&sm[OFF_F +  l      *FS + px    ];
            ull A1 = *(const ull*)&sm[OFF_F +  l      *FS + px + 2];
            ull B0 = *(const ull*)&sm[OFF_F + (l + 32)*FS + px    ];
            ull B1 = *(const ull*)&sm[OFF_F + (l + 32)*FS + px + 2];
            #pragma unroll
            for (int k = 0; k < 9; k++) {
                ulonglong2 wv = *(const ulonglong2*)&sm[OFF_W + k*132 + px]; // broadcast
                ffma2(m[k],     wv.x, A0);
                ffma2(m[k],     wv.y, A1);
                ffma2(m[k + 9], wv.x, B0);
                ffma2(m[k + 9], wv.y, B1);
            }
        }
    }
    __syncthreads();   // all f reads done -> overlay partials on f region

    {   // scalar partials: group-row, slot = k*64 + channel (conflict-free STS.32)
        float* part = &sm[OFF_F];
        #pragma unroll
        for (int k = 0; k < 9; k++) {
            float a, b;
            f2_unpack(m[k], a, b);
            part[(size_t)grp*PSTRIDE + k*64 + l]      = a + b;
            f2_unpack(m[k+9], a, b);
            part[(size_t)grp*PSTRIDE + k*64 + l + 32] = a + b;
        }
    }
    __syncthreads();

    {   // reduce 576 slots over 4 groups, then global RED.ADD
        const float* part = &sm[OFF_F];
        for (int s = tid; s < 576; s += 128) {
            float sum = part[s];
            #pragma unroll
            for (int g = 1; g < 4; g++) sum += part[(size_t)g*PSTRIDE + s];
            int k = s >> 6, c = s & 63;
            int nb = (vmask >> k & 1) ? nbr_of(R, Cc, k) : 0;
            atomicAdd(&g_numer[(bb*NSPIX + nb)*Cn + c], sum);  // invalid k adds 0.0
        }
    }
}

// ---------------------------------------------------------------------------
__global__ void update_kernel(float* __restrict__ out_spix, int it, int last)
{
    int idx = blockIdx.x*256 + threadIdx.x;     // 65536
    int par = it & 1;
    float val = g_numer[idx] / (g_denom2[par][idx >> 6] + 1e-16f);
    g_spix[idx] = val;
    if (last) out_spix[idx] = val;
    g_numer[idx] = 0.f;
    if (idx < Bn*NSPIX) g_denom2[1 - par][idx] = 0.f;
}

// ---------------------------------------------------------------------------
extern "C" void kernel_launch(void* const* d_in, const int* in_sizes, int n_in,
                              void* d_out, int out_size)
{
    const float* f = (const float*)d_in[0];
    float* out        = (float*)d_out;
    float* out_spix   = out;                       // (4,256,64)
    float* out_labels = out + Bn*NSPIX*Cn;         // (4,262144)

    cudaFuncSetAttribute(ssn_iter_kernel,
                         cudaFuncAttributeMaxDynamicSharedMemorySize, SMEM_BYTES);

    init_kernel<<<dim3(NSPIX, Bn), 256>>>(f);
    for (int it = 0; it < 5; it++) {
        ssn_iter_kernel<<<dim3(8, NSPIX, Bn), 128, SMEM_BYTES>>>(
            f, out_labels, it, it == 4);
        update_kernel<<<256, 256>>>(out_spix, it, it == 4);
    }
}

// round 9
// speedup vs baseline: 1.2485x; 1.0069x over previous
#include <cuda_runtime.h>
#include <cstddef>

#define Bn     4
#define Cn     64
#define Hn     512
#define Wn     512
#define NSPIX  256
#define HW     (Hn*Wn)

typedef unsigned long long ull;

// scratch
__device__ float g_spix [Bn*NSPIX*Cn];
__device__ float g_numer[Bn*NSPIX*Cn];
__device__ float g_denom2[2][Bn*NSPIX];

// ---- packed fp32x2 helpers ----
__device__ __forceinline__ ull f2_pack(float a, float b) {
    ull r; asm("mov.b64 %0, {%1,%2};" : "=l"(r) : "f"(a), "f"(b)); return r;
}
__device__ __forceinline__ void f2_unpack(ull v, float& a, float& b) {
    asm("mov.b64 {%0,%1}, %2;" : "=f"(a), "=f"(b) : "l"(v));
}
__device__ __forceinline__ void ffma2(ull& d, ull a, ull b) {
    asm("fma.rn.f32x2 %0, %1, %2, %0;" : "+l"(d) : "l"(a), "l"(b));
}

// shared layout (float offsets), 128-px tile, W overlays G (disjoint lifetimes)
#define OFF_G    0                      // [9][64] centroids (dead after phase-1 dots)
#define OFF_W    0                      // [9][128] weights (written after G dies)
#define OFF_GSQ  1152                   // [16]
#define OFF_DRED 1168                   // [9][4] + pad to 1216 (16B align)
#define OFF_F    1216                   // [64][130] pixel-scalar floats
#define FS       130                    // FS/2=65 odd -> pair reads conflict-free
#define SMEM_FLOATS (1216 + 64*FS)      // 9536 floats = 38144 B  (6 CTAs/SM)
#define SMEM_BYTES  (SMEM_FLOATS*4)
#define PSTRIDE 584                     // partial stride per warp-group (overlay on f)

__device__ __forceinline__ int nbr_of(int R, int Cc, int k) {
    return (R + k/3 - 1)*16 + (Cc + k%3 - 1);
}

// ---------------------------------------------------------------------------
__global__ void init_kernel(const float* __restrict__ f)
{
    __shared__ float sm[256];
    const int s = blockIdx.x, b = blockIdx.y;
    const int tid = threadIdx.x;
    const int c = tid & 63, part = tid >> 6;
    const int R = s >> 4, Cc = s & 15;
    const int y0 = R*32 + part*8, x0 = Cc*32;
    const float* fp = f + ((size_t)(b*Cn + c))*HW + (size_t)y0*Wn + x0;

    float sum = 0.f;
    for (int yy = 0; yy < 8; yy++) {
        const float4* r = (const float4*)(fp + (size_t)yy*Wn);
        #pragma unroll
        for (int x4 = 0; x4 < 8; x4++) {
            float4 v = r[x4];
            sum += (v.x + v.y) + (v.z + v.w);
        }
    }
    sm[tid] = sum;

    int gid = ((blockIdx.y*gridDim.x) + blockIdx.x)*256 + tid;
    if (gid < Bn*NSPIX*Cn) g_numer[gid] = 0.f;
    if (gid < 2*Bn*NSPIX)  ((float*)g_denom2)[gid] = 0.f;

    __syncthreads();
    if (tid < 64) {
        float t = sm[tid] + sm[64+tid] + sm[128+tid] + sm[192+tid];
        g_spix[(b*NSPIX + s)*Cn + tid] = t * (1.0f/1024.0f);
    }
}

// ---------------------------------------------------------------------------
// fused iteration kernel.  grid=(8,256,4)  block=128 (4x32 pixel tile)
// ---------------------------------------------------------------------------
__global__ __launch_bounds__(128, 6)
void ssn_iter_kernel(const float* __restrict__ f,
                     float* __restrict__ out_labels,
                     int it, int last)
{
    extern __shared__ float sm[];
    const int tid = threadIdx.x;
    const int bb = blockIdx.z, cell = blockIdx.y, q = blockIdx.x;
    const int R = cell >> 4, Cc = cell & 15;
    const int y0 = R*32 + q*4, x0 = Cc*32;
    const int par = it & 1;

    unsigned vmask = 0;
    #pragma unroll
    for (int k = 0; k < 9; k++) {
        int rr = R + k/3 - 1, cc = Cc + (k%3) - 1;
        if ((rr >= 0) & (rr < 16) & (cc >= 0) & (cc < 16)) vmask |= 1u << k;
    }

    // stage g (zero-filled invalid)
    for (int idx = tid; idx < 576; idx += 128) {
        int k = idx >> 6;
        int nb = nbr_of(R, Cc, k);
        sm[OFF_G + idx] = (vmask >> k & 1)
            ? g_spix[(bb*NSPIX + nb)*Cn + (idx & 63)] : 0.f;
    }
    __syncthreads();

    if (tid < 9) {                       // ||g||^2 -> separate GSQ region
        float s = 0.f;
        #pragma unroll 8
        for (int c = 0; c < 64; c++) { float gv = sm[OFF_G + tid*64 + c]; s += gv*gv; }
        sm[OFF_GSQ + tid] = s;
    }

    // ---- phase 1: per-pixel stream; scalar staging; channel-packed dots
    const int p = tid;
    ull acc[9], sv = 0ull;
    #pragma unroll
    for (int k = 0; k < 9; k++) acc[k] = 0ull;
    {
        const float* fp = f + ((size_t)bb*Cn)*HW
                            + (size_t)(y0 + (p >> 5))*Wn + (x0 + (p & 31));
        #pragma unroll 4
        for (int cs = 0; cs < 16; cs++) {
            const int c = cs*4;
            float v0 = fp[(size_t)(c+0)*HW];
            float v1 = fp[(size_t)(c+1)*HW];
            float v2 = fp[(size_t)(c+2)*HW];
            float v3 = fp[(size_t)(c+3)*HW];
            sm[OFF_F + (c+0)*FS + p] = v0;      // conflict-free STS.32
            sm[OFF_F + (c+1)*FS + p] = v1;
            sm[OFF_F + (c+2)*FS + p] = v2;
            sm[OFF_F + (c+3)*FS + p] = v3;
            ull p01 = f2_pack(v0, v1);
            ull p23 = f2_pack(v2, v3);
            ffma2(sv, p01, p01);
            ffma2(sv, p23, p23);
            #pragma unroll
            for (int k = 0; k < 9; k++) {
                ulonglong2 g2 = *(const ulonglong2*)&sm[OFF_G + k*64 + c];  // broadcast
                ffma2(acc[k], p01, g2.x);
                ffma2(acc[k], p23, g2.y);
            }
        }
    }
    __syncthreads();   // gsq ready; f tile complete; G dead from here (W overlays)

    // ---- softmax per pixel (registers)
    float w[9];
    {
        float sa, sb; f2_unpack(sv, sa, sb);
        const float sv_s = sa + sb;
        float dmin = 3.0e38f;
        #pragma unroll
        for (int k = 0; k < 9; k++) {
            float a, b; f2_unpack(acc[k], a, b);
            float d = (vmask >> k & 1) ? (sv_s - 2.f*(a+b) + sm[OFF_GSQ + k]) : 3.0e38f;
            w[k] = d;
            dmin = fminf(dmin, d);
        }
        if (last) {
            int kb = 0; float bd = w[0];
            #pragma unroll
            for (int k = 1; k < 9; k++) if (w[k] < bd) { bd = w[k]; kb = k; }
            out_labels[(size_t)bb*HW + (size_t)(y0 + (p>>5))*Wn + (x0 + (p&31))]
                = (float)nbr_of(R, Cc, kb);
        }
        float s = 0.f;
        #pragma unroll
        for (int k = 0; k < 9; k++) { float e = __expf(dmin - w[k]); w[k] = e; s += e; }
        float inv = 1.f / s;
        #pragma unroll
        for (int k = 0; k < 9; k++) w[k] *= inv;
    }

    // scalar weight store (overlays dead G; conflict-free STS.32)
    #pragma unroll
    for (int k = 0; k < 9; k++) sm[OFF_W + k*128 + p] = w[k];

    // denominators: 9 block-wide sums -> DRED region
    #pragma unroll
    for (int k = 0; k < 9; k++) {
        float s = w[k];
        s += __shfl_down_sync(0xffffffffu, s, 16);
        s += __shfl_down_sync(0xffffffffu, s, 8);
        s += __shfl_down_sync(0xffffffffu, s, 4);
        s += __shfl_down_sync(0xffffffffu, s, 2);
        s += __shfl_down_sync(0xffffffffu, s, 1);
        if ((tid & 31) == 0) sm[OFF_DRED + k*4 + (tid >> 5)] = s;
    }
    __syncthreads();   // w + dred visible
    if (tid < 9 && (vmask >> tid & 1)) {
        const float* dr = &sm[OFF_DRED + tid*4];
        float s = (dr[0] + dr[1]) + (dr[2] + dr[3]);
        atomicAdd(&g_denom2[par][bb*NSPIX + nbr_of(R, Cc, tid)], s);
    }

    // ---- phase 2: pixel-pair packed, no packs, no shared atomics
    // lane = channels (l, l+32); warp grp owns 32 pixels (16 pairs)
    const int l   = tid & 31;
    const int grp = tid >> 5;
    ull m[18];
    #pragma unroll
    for (int k = 0; k < 18; k++) m[k] = 0ull;
    {
        const int pb = grp*32;
        #pragma unroll 2
        for (int jp = 0; jp < 8; jp++) {
            const int px = pb + jp*4;        // 4 pixels = 2 pairs per step
            ull A0 = *(const ull*)&sm[OFF_F +  l      *FS + px    ];
            ull A1 = *(const ull*)&sm[OFF_F +  l      *FS + px + 2];
            ull B0 = *(const ull*)&sm[OFF_F + (l + 32)*FS + px    ];
            ull B1 = *(const ull*)&sm[OFF_F + (l + 32)*FS + px + 2];
            #pragma unroll
            for (int k = 0; k < 9; k++) {
                ulonglong2 wv = *(const ulonglong2*)&sm[OFF_W + k*128 + px]; // broadcast
                ffma2(m[k],     wv.x, A0);
                ffma2(m[k],     wv.y, A1);
                ffma2(m[k + 9], wv.x, B0);
                ffma2(m[k + 9], wv.y, B1);
            }
        }
    }
    __syncthreads();   // all f reads done -> overlay partials on f region

    {   // scalar partials: group-row, slot = k*64 + channel (conflict-free STS.32)
        float* part = &sm[OFF_F];
        #pragma unroll
        for (int k = 0; k < 9; k++) {
            float a, b;
            f2_unpack(m[k], a, b);
            part[(size_t)grp*PSTRIDE + k*64 + l]      = a + b;
            f2_unpack(m[k+9], a, b);
            part[(size_t)grp*PSTRIDE + k*64 + l + 32] = a + b;
        }
    }
    __syncthreads();

    {   // reduce 576 slots over 4 groups, then global RED.ADD
        const float* part = &sm[OFF_F];
        for (int s = tid; s < 576; s += 128) {
            float sum = part[s];
            #pragma unroll
            for (int g = 1; g < 4; g++) sum += part[(size_t)g*PSTRIDE + s];
            int k = s >> 6, c = s & 63;
            int nb = (vmask >> k & 1) ? nbr_of(R, Cc, k) : 0;
            atomicAdd(&g_numer[(bb*NSPIX + nb)*Cn + c], sum);  // invalid k adds 0.0
        }
    }
}

// ---------------------------------------------------------------------------
__global__ void update_kernel(float* __restrict__ out_spix, int it, int last)
{
    int idx = blockIdx.x*256 + threadIdx.x;     // 65536
    int par = it & 1;
    float val = g_numer[idx] / (g_denom2[par][idx >> 6] + 1e-16f);
    g_spix[idx] = val;
    if (last) out_spix[idx] = val;
    g_numer[idx] = 0.f;
    if (idx < Bn*NSPIX) g_denom2[1 - par][idx] = 0.f;
}

// ---------------------------------------------------------------------------
extern "C" void kernel_launch(void* const* d_in, const int* in_sizes, int n_in,
                              void* d_out, int out_size)
{
    const float* f = (const float*)d_in[0];
    float* out        = (float*)d_out;
    float* out_spix   = out;                       // (4,256,64)
    float* out_labels = out + Bn*NSPIX*Cn;         // (4,262144)

    cudaFuncSetAttribute(ssn_iter_kernel,
                         cudaFuncAttributeMaxDynamicSharedMemorySize, SMEM_BYTES);

    init_kernel<<<dim3(NSPIX, Bn), 256>>>(f);
    for (int it = 0; it < 5; it++) {
        ssn_iter_kernel<<<dim3(8, NSPIX, Bn), 128, SMEM_BYTES>>>(
            f, out_labels, it, it == 4);
        update_kernel<<<256, 256>>>(out_spix, it, it == 4);
    }
}

// round 10
// speedup vs baseline: 1.3184x; 1.0560x over previous
#include <cuda_runtime.h>
#include <cstddef>

#define Bn     4
#define Cn     64
#define Hn     512
#define Wn     512
#define NSPIX  256
#define HW     (Hn*Wn)

typedef unsigned long long ull;

// scratch
__device__ float g_spix [Bn*NSPIX*Cn];
__device__ float g_numer[Bn*NSPIX*Cn];
__device__ float g_denom2[2][Bn*NSPIX];

// ---- packed fp32x2 helpers ----
__device__ __forceinline__ ull f2_pack(float a, float b) {
    ull r; asm("mov.b64 %0, {%1,%2};" : "=l"(r) : "f"(a), "f"(b)); return r;
}
__device__ __forceinline__ void f2_unpack(ull v, float& a, float& b) {
    asm("mov.b64 {%0,%1}, %2;" : "=f"(a), "=f"(b) : "l"(v));
}
__device__ __forceinline__ void ffma2(ull& d, ull a, ull b) {
    asm("fma.rn.f32x2 %0, %1, %2, %0;" : "+l"(d) : "l"(a), "l"(b));
}
__device__ __forceinline__ void fadd2(ull& d, ull a) {
    asm("add.rn.f32x2 %0, %0, %1;" : "+l"(d) : "l"(a));
}

// shared layout (float offsets), 128-px tile; W (8 rows) overlays dead G
#define OFF_G    0                      // [9][64] centroids (dead after phase-1 dots)
#define OFF_W    0                      // [8][128] weights k<8 (written after G dies)
#define OFF_GSQ  1024                   // [12]
#define OFF_DRED 1036                   // [9][4]
#define OFF_F    1072                   // [64][130] pixel-scalar floats
#define FS       130                    // FS/2=65 odd -> pair reads conflict-free
#define SMEM_FLOATS (1072 + 64*FS)      // 9392 floats = 37568 B  (6 CTAs/SM)
#define SMEM_BYTES  (SMEM_FLOATS*4)
#define PSTRIDE 584                     // partial stride per warp-group (overlay on f)

__device__ __forceinline__ int nbr_of(int R, int Cc, int k) {
    return (R + k/3 - 1)*16 + (Cc + k%3 - 1);
}

// ---------------------------------------------------------------------------
__global__ void init_kernel(const float* __restrict__ f)
{
    __shared__ float sm[256];
    const int s = blockIdx.x, b = blockIdx.y;
    const int tid = threadIdx.x;
    const int c = tid & 63, part = tid >> 6;
    const int R = s >> 4, Cc = s & 15;
    const int y0 = R*32 + part*8, x0 = Cc*32;
    const float* fp = f + ((size_t)(b*Cn + c))*HW + (size_t)y0*Wn + x0;

    float sum = 0.f;
    for (int yy = 0; yy < 8; yy++) {
        const float4* r = (const float4*)(fp + (size_t)yy*Wn);
        #pragma unroll
        for (int x4 = 0; x4 < 8; x4++) {
            float4 v = r[x4];
            sum += (v.x + v.y) + (v.z + v.w);
        }
    }
    sm[tid] = sum;

    int gid = ((blockIdx.y*gridDim.x) + blockIdx.x)*256 + tid;
    if (gid < Bn*NSPIX*Cn) g_numer[gid] = 0.f;
    if (gid < 2*Bn*NSPIX)  ((float*)g_denom2)[gid] = 0.f;

    __syncthreads();
    if (tid < 64) {
        float t = sm[tid] + sm[64+tid] + sm[128+tid] + sm[192+tid];
        g_spix[(b*NSPIX + s)*Cn + tid] = t * (1.0f/1024.0f);
    }
}

// ---------------------------------------------------------------------------
// fused iteration kernel.  grid=(8,256,4)  block=128 (4x32 pixel tile)
// ---------------------------------------------------------------------------
__global__ __launch_bounds__(128, 6)
void ssn_iter_kernel(const float* __restrict__ f,
                     float* __restrict__ out_labels,
                     int it, int last)
{
    extern __shared__ float sm[];
    const int tid = threadIdx.x;
    const int bb = blockIdx.z, cell = blockIdx.y, q = blockIdx.x;
    const int R = cell >> 4, Cc = cell & 15;
    const int y0 = R*32 + q*4, x0 = Cc*32;
    const int par = it & 1;

    unsigned vmask = 0;
    #pragma unroll
    for (int k = 0; k < 9; k++) {
        int rr = R + k/3 - 1, cc = Cc + (k%3) - 1;
        if ((rr >= 0) & (rr < 16) & (cc >= 0) & (cc < 16)) vmask |= 1u << k;
    }

    // stage g (zero-filled invalid)
    for (int idx = tid; idx < 576; idx += 128) {
        int k = idx >> 6;
        int nb = nbr_of(R, Cc, k);
        sm[OFF_G + idx] = (vmask >> k & 1)
            ? g_spix[(bb*NSPIX + nb)*Cn + (idx & 63)] : 0.f;
    }
    __syncthreads();

    if (tid < 9) {                       // ||g||^2
        float s = 0.f;
        #pragma unroll 8
        for (int c = 0; c < 64; c++) { float gv = sm[OFF_G + tid*64 + c]; s += gv*gv; }
        sm[OFF_GSQ + tid] = s;
    }

    // ---- phase 1: per-pixel stream; scalar staging; channel-packed dots
    const int p = tid;
    ull acc[9], sv = 0ull;
    #pragma unroll
    for (int k = 0; k < 9; k++) acc[k] = 0ull;
    {
        const float* fp = f + ((size_t)bb*Cn)*HW
                            + (size_t)(y0 + (p >> 5))*Wn + (x0 + (p & 31));
        #pragma unroll 4
        for (int cs = 0; cs < 16; cs++) {
            const int c = cs*4;
            float v0 = fp[(size_t)(c+0)*HW];
            float v1 = fp[(size_t)(c+1)*HW];
            float v2 = fp[(size_t)(c+2)*HW];
            float v3 = fp[(size_t)(c+3)*HW];
            sm[OFF_F + (c+0)*FS + p] = v0;      // conflict-free STS.32
            sm[OFF_F + (c+1)*FS + p] = v1;
            sm[OFF_F + (c+2)*FS + p] = v2;
            sm[OFF_F + (c+3)*FS + p] = v3;
            ull p01 = f2_pack(v0, v1);
            ull p23 = f2_pack(v2, v3);
            ffma2(sv, p01, p01);
            ffma2(sv, p23, p23);
            #pragma unroll
            for (int k = 0; k < 9; k++) {
                ulonglong2 g2 = *(const ulonglong2*)&sm[OFF_G + k*64 + c];  // broadcast
                ffma2(acc[k], p01, g2.x);
                ffma2(acc[k], p23, g2.y);
            }
        }
    }
    __syncthreads();   // gsq ready; f tile complete; G dead from here (W overlays)

    // ---- softmax per pixel (registers)
    float w[9];
    {
        float sa, sb; f2_unpack(sv, sa, sb);
        const float sv_s = sa + sb;
        float dmin = 3.0e38f;
        #pragma unroll
        for (int k = 0; k < 9; k++) {
            float a, b; f2_unpack(acc[k], a, b);
            float d = (vmask >> k & 1) ? (sv_s - 2.f*(a+b) + sm[OFF_GSQ + k]) : 3.0e38f;
            w[k] = d;
            dmin = fminf(dmin, d);
        }
        if (last) {
            int kb = 0; float bd = w[0];
            #pragma unroll
            for (int k = 1; k < 9; k++) if (w[k] < bd) { bd = w[k]; kb = k; }
            out_labels[(size_t)bb*HW + (size_t)(y0 + (p>>5))*Wn + (x0 + (p&31))]
                = (float)nbr_of(R, Cc, kb);
        }
        float s = 0.f;
        #pragma unroll
        for (int k = 0; k < 9; k++) { float e = __expf(dmin - w[k]); w[k] = e; s += e; }
        float inv = 1.f / s;
        #pragma unroll
        for (int k = 0; k < 9; k++) w[k] *= inv;
    }

    // store only w[0..7] (w[8] reconstructed from sum rule in phase 2)
    #pragma unroll
    for (int k = 0; k < 8; k++) sm[OFF_W + k*128 + p] = w[k];

    // denominators: 9 block-wide sums (exact register weights)
    #pragma unroll
    for (int k = 0; k < 9; k++) {
        float s = w[k];
        s += __shfl_down_sync(0xffffffffu, s, 16);
        s += __shfl_down_sync(0xffffffffu, s, 8);
        s += __shfl_down_sync(0xffffffffu, s, 4);
        s += __shfl_down_sync(0xffffffffu, s, 2);
        s += __shfl_down_sync(0xffffffffu, s, 1);
        if ((tid & 31) == 0) sm[OFF_DRED + k*4 + (tid >> 5)] = s;
    }
    __syncthreads();   // w + dred visible
    if (tid < 9 && (vmask >> tid & 1)) {
        const float* dr = &sm[OFF_DRED + tid*4];
        float s = (dr[0] + dr[1]) + (dr[2] + dr[3]);
        atomicAdd(&g_denom2[par][bb*NSPIX + nbr_of(R, Cc, tid)], s);
    }

    // ---- phase 2: 8 weighted rows + unweighted pixel-sum row
    // lane = channels (l, l+32); warp grp owns 32 pixels (16 pairs)
    const int l   = tid & 31;
    const int grp = tid >> 5;
    ull m[16], msA = 0ull, msB = 0ull;
    #pragma unroll
    for (int k = 0; k < 16; k++) m[k] = 0ull;
    {
        const int pb = grp*32;
        #pragma unroll 2
        for (int jp = 0; jp < 8; jp++) {
            const int px = pb + jp*4;        // 4 pixels = 2 pairs per step
            ull A0 = *(const ull*)&sm[OFF_F +  l      *FS + px    ];
            ull A1 = *(const ull*)&sm[OFF_F +  l      *FS + px + 2];
            ull B0 = *(const ull*)&sm[OFF_F + (l + 32)*FS + px    ];
            ull B1 = *(const ull*)&sm[OFF_F + (l + 32)*FS + px + 2];
            fadd2(msA, A0); fadd2(msA, A1);
            fadd2(msB, B0); fadd2(msB, B1);
            #pragma unroll
            for (int k = 0; k < 8; k++) {
                ulonglong2 wv = *(const ulonglong2*)&sm[OFF_W + k*128 + px]; // broadcast
                ffma2(m[k],     wv.x, A0);
                ffma2(m[k],     wv.y, A1);
                ffma2(m[k + 8], wv.x, B0);
                ffma2(m[k + 8], wv.y, B1);
            }
        }
    }
    __syncthreads();   // all f reads done -> overlay partials on f region

    {   // scalar partials; slot 8 via sum rule: M8 = sum_p f - sum_{k<8} Mk
        float* part = &sm[OFF_F];
        float a, b, sA = 0.f, sB = 0.f;
        #pragma unroll
        for (int k = 0; k < 8; k++) {
            f2_unpack(m[k], a, b);
            float pk = a + b;
            part[(size_t)grp*PSTRIDE + k*64 + l] = pk;
            sA += pk;
            f2_unpack(m[k+8], a, b);
            pk = a + b;
            part[(size_t)grp*PSTRIDE + k*64 + l + 32] = pk;
            sB += pk;
        }
        f2_unpack(msA, a, b);
        part[(size_t)grp*PSTRIDE + 8*64 + l]      = (a + b) - sA;
        f2_unpack(msB, a, b);
        part[(size_t)grp*PSTRIDE + 8*64 + l + 32] = (a + b) - sB;
    }
    __syncthreads();

    {   // reduce 576 slots over 4 groups, then global RED.ADD
        const float* part = &sm[OFF_F];
        for (int s = tid; s < 576; s += 128) {
            float sum = part[s];
            #pragma unroll
            for (int g = 1; g < 4; g++) sum += part[(size_t)g*PSTRIDE + s];
            int k = s >> 6, c = s & 63;
            int nb = (vmask >> k & 1) ? nbr_of(R, Cc, k) : 0;
            atomicAdd(&g_numer[(bb*NSPIX + nb)*Cn + c], sum);  // invalid k adds 0.0
        }
    }
}

// ---------------------------------------------------------------------------
__global__ void update_kernel(float* __restrict__ out_spix, int it, int last)
{
    int idx = blockIdx.x*256 + threadIdx.x;     // 65536
    int par = it & 1;
    float val = g_numer[idx] / (g_denom2[par][idx >> 6] + 1e-16f);
    g_spix[idx] = val;
    if (last) out_spix[idx] = val;
    g_numer[idx] = 0.f;
    if (idx < Bn*NSPIX) g_denom2[1 - par][idx] = 0.f;
}

// ---------------------------------------------------------------------------
extern "C" void kernel_launch(void* const* d_in, const int* in_sizes, int n_in,
                              void* d_out, int out_size)
{
    const float* f = (const float*)d_in[0];
    float* out        = (float*)d_out;
    float* out_spix   = out;                       // (4,256,64)
    float* out_labels = out + Bn*NSPIX*Cn;         // (4,262144)

    cudaFuncSetAttribute(ssn_iter_kernel,
                         cudaFuncAttributeMaxDynamicSharedMemorySize, SMEM_BYTES);

    init_kernel<<<dim3(NSPIX, Bn), 256>>>(f);
    for (int it = 0; it < 5; it++) {
        ssn_iter_kernel<<<dim3(8, NSPIX, Bn), 128, SMEM_BYTES>>>(
            f, out_labels, it, it == 4);
        update_kernel<<<256, 256>>>(out_spix, it, it == 4);
    }
}